// round 4
// baseline (speedup 1.0000x reference)
#include <cuda_runtime.h>
#include <math.h>

// z[b] = sum_t x[b,t]*K[t] + z0 + e
// K[t] = sum_h w_h*b_h*a_h^(T-1-t),  z0 = sum_h w_h*c_h*(1-a_h^T)/(1-a_h)
#define TLEN 4096
#define HDIM 512
#define BATCH 64
#define CHUNK 16
#define NCHUNK (TLEN / CHUNK)   // 256 blocks

// Scratch (__device__ globals; no allocations allowed)
__device__ float g_part[BATCH * NCHUNK];  // [row][chunk] partial dots
__device__ float g_z0;
__device__ int   g_ctr;                   // zero-init; reset by finalizer each run

__global__ __launch_bounds__(HDIM) void fused_kernel(
    const float* __restrict__ x, const float* __restrict__ a,
    const float* __restrict__ b, const float* __restrict__ c,
    const float* __restrict__ w, const float* __restrict__ e,
    float* __restrict__ out)
{
    __shared__ float part[CHUNK][HDIM];   // 32 KB
    __shared__ float kc[CHUNK];
    __shared__ float zp[16];
    __shared__ int   s_last;

    const int tid  = threadIdx.x;
    const int j    = blockIdx.x;          // exponent chunk: s in [16j, 16j+16)
    const int warp = tid >> 5, lane = tid & 31;
    const int row  = tid >> 3, sub  = tid & 7;   // dot layout: 8 threads per batch row

    // ---- prefetch this block's x window (overlaps with K compute) ----
    // exponent s = 16j+i maps to t = 4095-s; block j covers t in [t0, t0+16)
    const int t0 = TLEN - CHUNK * (j + 1);
    const float2 xv = *(const float2*)(x + (size_t)row * TLEN + t0 + 2 * sub);

    // ---- phase 1: K chunk. Seed wb * a^(16j) via accurate log2f/exp2f ----
    const float af  = a[tid];
    const float wb  = w[tid] * b[tid];
    const float l2a = log2f(af);                       // relative-accurate (NOT __log2f)
    float p = wb * exp2f((float)(j * CHUNK) * l2a);

    #pragma unroll
    for (int i = 0; i < CHUNK; i++) { part[i][tid] = p; p *= af; }

    // block 0 additionally computes z0 (all fp32)
    if (j == 0) {
        const float aT   = exp2f((float)TLEN * l2a);
        const float geo  = (1.0f - aT) / (1.0f - af);
        float term = w[tid] * c[tid] * geo;
        #pragma unroll
        for (int off = 16; off; off >>= 1)
            term += __shfl_down_sync(0xffffffffu, term, off);
        if (lane == 0) zp[warp] = term;
    }
    __syncthreads();

    // reduce across h: warp i produces kc[i] (t-offset within chunk)
    float s = 0.0f;
    #pragma unroll
    for (int k = 0; k < HDIM / 32; k++) s += part[warp][lane + 32 * k];
    #pragma unroll
    for (int off = 16; off; off >>= 1) s += __shfl_down_sync(0xffffffffu, s, off);
    if (lane == 0) kc[warp] = s;

    if (j == 0 && tid == 0) {
        float sz = 0.0f;
        #pragma unroll
        for (int i = 0; i < 16; i++) sz += zp[i];
        g_z0 = sz;
    }
    __syncthreads();

    // ---- phase 2: dot contribution of this block's 16 t's, all 64 rows ----
    // x element at t = t0+u pairs with kc[15-u]; thread covers u = 2*sub, 2*sub+1
    float d = xv.x * kc[15 - 2 * sub] + xv.y * kc[14 - 2 * sub];
    d += __shfl_down_sync(0xffffffffu, d, 4, 8);
    d += __shfl_down_sync(0xffffffffu, d, 2, 8);
    d += __shfl_down_sync(0xffffffffu, d, 1, 8);
    if (sub == 0) g_part[row * NCHUNK + j] = d;

    // ---- tail-block finalize ----
    __threadfence();
    __syncthreads();
    if (tid == 0) {
        int t = atomicAdd(&g_ctr, 1);
        s_last = (t == NCHUNK - 1);
    }
    __syncthreads();
    if (!s_last) return;

    __threadfence();   // acquire: all g_part / g_z0 writes are L2-visible
    {
        // thread layout: 8 threads per row, each sums 32 consecutive partials
        const int base = row * NCHUNK + sub * 32;
        float acc = 0.0f;
        #pragma unroll
        for (int k = 0; k < 32; k++) acc += __ldcg(&g_part[base + k]);
        acc += __shfl_down_sync(0xffffffffu, acc, 4, 8);
        acc += __shfl_down_sync(0xffffffffu, acc, 2, 8);
        acc += __shfl_down_sync(0xffffffffu, acc, 1, 8);
        if (sub == 0) out[row] = acc + __ldcg(&g_z0) + e[0];
    }
    __syncthreads();
    if (tid == 0) g_ctr = 0;   // reset for next graph replay
}

extern "C" void kernel_launch(void* const* d_in, const int* in_sizes, int n_in,
                              void* d_out, int out_size)
{
    const float* x = (const float*)d_in[0];   // [B, T]
    const float* a = (const float*)d_in[1];   // [H]
    const float* b = (const float*)d_in[2];   // [H]
    const float* c = (const float*)d_in[3];   // [H]
    const float* w = (const float*)d_in[4];   // [H]
    const float* e = (const float*)d_in[5];   // [1]
    float* out = (float*)d_out;               // [B]

    fused_kernel<<<NCHUNK, HDIM>>>(x, a, b, c, w, e, out);
}

// round 5
// speedup vs baseline: 1.8897x; 1.8897x over previous
#include <cuda_runtime.h>
#include <math.h>

// z[b] = sum_t x[b,t]*K[t] + z0 + e
// K[t] = sum_h w_h*b_h*a_h^(T-1-t),  z0 = sum_h w_h*c_h*(1-a_h^T)/(1-a_h)
#define TLEN 4096
#define HDIM 512
#define BATCH 64
#define CHUNK 16
#define NCHUNK (TLEN / CHUNK)   // 256 blocks

// Scratch (__device__ globals; no allocations allowed)
__device__ __align__(16) float g_K[TLEN];
__device__ float g_z0;

// Kernel 1: K chunk of 16 t's per block. Seed wb*a^(16j) via accurate
// log2f/exp2f (relative-accurate libm versions, NOT __log2f). All fp32.
__global__ __launch_bounds__(HDIM) void build_K_kernel(
    const float* __restrict__ a, const float* __restrict__ b,
    const float* __restrict__ c, const float* __restrict__ w)
{
    __shared__ float part[CHUNK][HDIM];   // 32 KB
    const int h = threadIdx.x;
    const int j = blockIdx.x;             // exponents s in [16j, 16j+16)
    const int warp = h >> 5, lane = h & 31;

    const float af  = a[h];
    const float wb  = w[h] * b[h];
    const float l2a = log2f(af);
    float p = wb * exp2f((float)(j * CHUNK) * l2a);

    #pragma unroll
    for (int i = 0; i < CHUNK; i++) { part[i][h] = p; p *= af; }

    // block 0: z0 = sum_h w*c*(1-a^T)/(1-a)   (pure fp32)
    __shared__ float zp[16];
    if (j == 0) {
        const float aT  = exp2f((float)TLEN * l2a);
        const float geo = (1.0f - aT) / (1.0f - af);
        float term = w[h] * c[h] * geo;
        #pragma unroll
        for (int off = 16; off; off >>= 1)
            term += __shfl_down_sync(0xffffffffu, term, off);
        if (lane == 0) zp[warp] = term;
    }
    __syncthreads();

    // reduce across h: warp i produces the value for t-offset i
    float s = 0.0f;
    #pragma unroll
    for (int k = 0; k < HDIM / 32; k++) s += part[warp][lane + 32 * k];
    #pragma unroll
    for (int off = 16; off; off >>= 1) s += __shfl_down_sync(0xffffffffu, s, off);
    if (lane == 0) g_K[TLEN - 1 - (j * CHUNK + warp)] = s;

    if (j == 0 && h == 0) {
        float sz = 0.0f;
        #pragma unroll
        for (int i = 0; i < 16; i++) sz += zp[i];
        g_z0 = sz;
    }
}

// Kernel 2: one block per batch row, 1024 threads, one float4 of x and K per
// thread (full row in flight -> max MLP), block reduce, write out directly.
__global__ __launch_bounds__(1024) void dot_kernel(
    const float* __restrict__ x, const float* __restrict__ e,
    float* __restrict__ out)
{
    const int row = blockIdx.x;
    const int tid = threadIdx.x;

    const float4 xv = ((const float4*)(x + (size_t)row * TLEN))[tid];
    const float4 kv = ((const float4*)g_K)[tid];

    float s = xv.x * kv.x + xv.y * kv.y + xv.z * kv.z + xv.w * kv.w;
    #pragma unroll
    for (int off = 16; off; off >>= 1) s += __shfl_down_sync(0xffffffffu, s, off);

    __shared__ float sp[32];
    const int warp = tid >> 5, lane = tid & 31;
    if (lane == 0) sp[warp] = s;
    __syncthreads();

    if (warp == 0) {
        float t = sp[lane];
        #pragma unroll
        for (int off = 16; off; off >>= 1) t += __shfl_down_sync(0xffffffffu, t, off);
        if (lane == 0) out[row] = t + g_z0 + e[0];
    }
}

extern "C" void kernel_launch(void* const* d_in, const int* in_sizes, int n_in,
                              void* d_out, int out_size)
{
    const float* x = (const float*)d_in[0];   // [B, T]
    const float* a = (const float*)d_in[1];   // [H]
    const float* b = (const float*)d_in[2];   // [H]
    const float* c = (const float*)d_in[3];   // [H]
    const float* w = (const float*)d_in[4];   // [H]
    const float* e = (const float*)d_in[5];   // [1]
    float* out = (float*)d_out;               // [B]

    build_K_kernel<<<NCHUNK, HDIM>>>(a, b, c, w);
    dot_kernel<<<BATCH, 1024>>>(x, e, out);
}

// round 6
// speedup vs baseline: 1.9179x; 1.0149x over previous
#include <cuda_runtime.h>
#include <math.h>

// z[b] = sum_t x[b,t]*K[t] + z0 + e
// K[t] = sum_h w_h*b_h*a_h^(T-1-t),  z0 = sum_h w_h*c_h*(1-a_h^T)/(1-a_h)
#define TLEN 4096
#define HDIM 512
#define BATCH 64
#define CHUNK 16
#define NCHUNK (TLEN / CHUNK)   // 256 blocks

// Scratch (__device__ globals; no allocations allowed)
__device__ __align__(16) float g_K[TLEN];
__device__ float g_z0;

// Kernel 1: K chunk of 16 t's per block, seed via accurate log2f/exp2f.
// Triggers the dependent (PDL) grid right after its K stores.
__global__ __launch_bounds__(HDIM) void build_K_kernel(
    const float* __restrict__ a, const float* __restrict__ b,
    const float* __restrict__ c, const float* __restrict__ w)
{
    __shared__ float part[CHUNK][HDIM];   // 32 KB
    __shared__ float zp[16];
    const int h = threadIdx.x;
    const int j = blockIdx.x;             // exponents s in [16j, 16j+16)
    const int warp = h >> 5, lane = h & 31;

    const float af  = a[h];
    const float wb  = w[h] * b[h];
    const float l2a = log2f(af);          // relative-accurate (NOT __log2f)
    float p = wb * exp2f((float)(j * CHUNK) * l2a);

    #pragma unroll
    for (int i = 0; i < CHUNK; i++) { part[i][h] = p; p *= af; }

    // block 0: z0 = sum_h w*c*(1-a^T)/(1-a)  (pure fp32)
    if (j == 0) {
        const float aT  = exp2f((float)TLEN * l2a);
        const float geo = (1.0f - aT) / (1.0f - af);
        float term = w[h] * c[h] * geo;
        #pragma unroll
        for (int off = 16; off; off >>= 1)
            term += __shfl_down_sync(0xffffffffu, term, off);
        if (lane == 0) zp[warp] = term;
    }
    __syncthreads();

    // reduce across h: warp i produces the value for t-offset i
    float s = 0.0f;
    #pragma unroll
    for (int k = 0; k < HDIM / 32; k++) s += part[warp][lane + 32 * k];
    #pragma unroll
    for (int off = 16; off; off >>= 1) s += __shfl_down_sync(0xffffffffu, s, off);
    if (lane == 0) g_K[TLEN - 1 - (j * CHUNK + warp)] = s;

    if (j == 0 && h == 0) {
        float sz = 0.0f;
        #pragma unroll
        for (int i = 0; i < 16; i++) sz += zp[i];
        g_z0 = sz;
    }

    // All K/z0 stores for this CTA are issued -> let the dependent grid run.
    asm volatile("griddepcontrol.launch_dependents;");
}

// Kernel 2 (PDL secondary): one block per batch row, 1024 threads.
// x/e loads issued BEFORE griddepcontrol.wait so they overlap build_K.
__global__ __launch_bounds__(1024) void dot_kernel(
    const float* __restrict__ x, const float* __restrict__ e,
    float* __restrict__ out)
{
    const int row = blockIdx.x;
    const int tid = threadIdx.x;

    // independent prologue: overlaps with the primary grid
    const float4 xv = ((const float4*)(x + (size_t)row * TLEN))[tid];
    const float ev = e[0];

    // wait for build_K's stores to become visible
    asm volatile("griddepcontrol.wait;" ::: "memory");

    const float4 kv = __ldcg(&((const float4*)g_K)[tid]);

    float s = xv.x * kv.x + xv.y * kv.y + xv.z * kv.z + xv.w * kv.w;
    #pragma unroll
    for (int off = 16; off; off >>= 1) s += __shfl_down_sync(0xffffffffu, s, off);

    __shared__ float sp[32];
    const int warp = tid >> 5, lane = tid & 31;
    if (lane == 0) sp[warp] = s;
    __syncthreads();

    if (warp == 0) {
        float t = sp[lane];
        #pragma unroll
        for (int off = 16; off; off >>= 1) t += __shfl_down_sync(0xffffffffu, t, off);
        if (lane == 0) out[row] = t + __ldcg(&g_z0) + ev;
    }
}

extern "C" void kernel_launch(void* const* d_in, const int* in_sizes, int n_in,
                              void* d_out, int out_size)
{
    const float* x = (const float*)d_in[0];   // [B, T]
    const float* a = (const float*)d_in[1];   // [H]
    const float* b = (const float*)d_in[2];   // [H]
    const float* c = (const float*)d_in[3];   // [H]
    const float* w = (const float*)d_in[4];   // [H]
    const float* e = (const float*)d_in[5];   // [1]
    float* out = (float*)d_out;               // [B]

    build_K_kernel<<<NCHUNK, HDIM>>>(a, b, c, w);

    // Launch dot as a programmatic dependent of build_K (PDL edge; graph-capturable)
    cudaLaunchAttribute attrs[1];
    attrs[0].id = cudaLaunchAttributeProgrammaticStreamSerialization;
    attrs[0].val.programmaticStreamSerializationAllowed = 1;
    cudaLaunchConfig_t cfg = {};
    cfg.gridDim  = dim3(BATCH);
    cfg.blockDim = dim3(1024);
    cfg.dynamicSmemBytes = 0;
    cfg.stream = 0;
    cfg.attrs = attrs;
    cfg.numAttrs = 1;
    cudaLaunchKernelEx(&cfg, dot_kernel, x, e, out);
}